// round 16
// baseline (speedup 1.0000x reference)
#include <cuda_runtime.h>
#include <cuda_fp16.h>
#include <cstdint>

#define N_NODES 100000
#define N_EDGES 3200000
#define D_IN 128
#define ATT 64
#define HEADS 4
#define NH (N_NODES * HEADS)
#define EH (N_EDGES * HEADS)
#define COLS 192
#define EQ (N_EDGES / 4)
#define EO (N_EDGES / 8)

// ---------------- scratch (device globals; no allocation) ----------------
__device__ __align__(128) __half g_qh[(size_t)N_NODES * ATT];   // fp16 q rows (128B/row)
__device__ __align__(128) __half g_kh[(size_t)N_NODES * ATT];   // fp16 k rows
__device__ __align__(128) __half g_xh[(size_t)N_NODES * D_IN];  // fp16 x (precomputed)
__device__ __align__(16)  float  g_sum[NH];
__device__ int g_is64;
// fused transposed weights fp16: Wt[m][d]
__device__ __align__(16) __half g_wth[COLS * D_IN];

// ---------------- fused prep: xh | zero | wconv | detect (one launch) ------
#define XH_CHUNKS   (N_NODES * D_IN / 8)                // 1.6M
#define XH_QUARTER  (XH_CHUNKS / 4)
#define XH_BLOCKS   ((XH_QUARTER + 255) / 256)          // 1563
#define ZERO_BLOCKS ((NH + 255) / 256)                  // 1563
#define WC_BLOCKS   ((COLS * D_IN + 255) / 256)         // 96
#define PREP_BLOCKS (XH_BLOCKS + ZERO_BLOCKS + WC_BLOCKS + 1)

__global__ void k_prep(const float* __restrict__ x,
                       const float* __restrict__ WQ, const float* __restrict__ WK,
                       const float* __restrict__ WV, const int* __restrict__ e32) {
    int b = blockIdx.x;
    if (b < XH_BLOCKS) {
        int i0 = b * 256 + threadIdx.x;
        if (i0 < XH_QUARTER) {
#pragma unroll
            for (int c = 0; c < 4; c++) {
                int i = i0 + c * XH_QUARTER;
                const float4* xp = (const float4*)(x + (size_t)i * 8);
                float4 v0 = xp[0], v1 = xp[1];
                __half hi[8];
                hi[0] = __float2half_rn(v0.x); hi[1] = __float2half_rn(v0.y);
                hi[2] = __float2half_rn(v0.z); hi[3] = __float2half_rn(v0.w);
                hi[4] = __float2half_rn(v1.x); hi[5] = __float2half_rn(v1.y);
                hi[6] = __float2half_rn(v1.z); hi[7] = __float2half_rn(v1.w);
                ((uint4*)g_xh)[i] = *(const uint4*)hi;
            }
        }
    } else if (b < XH_BLOCKS + ZERO_BLOCKS) {
        int j = (b - XH_BLOCKS) * 256 + threadIdx.x;
        if (j < NH) g_sum[j] = 0.0f;
    } else if (b < XH_BLOCKS + ZERO_BLOCKS + WC_BLOCKS) {
        int i = (b - XH_BLOCKS - ZERO_BLOCKS) * 256 + threadIdx.x;
        if (i < COLS * D_IN) {
            int m = i >> 7, d = i & 127;
            float w;
            if (m < 64)       w = WQ[d * 64 + m];
            else if (m < 128) w = WK[d * 64 + (m - 64)];
            else              w = WV[d * 64 + (m - 128)];
            g_wth[i] = __float2half_rn(w);
        }
    } else {
        // edge dtype detect: int64 edges (<1e5) have zero high words
        int any = 0;
        for (int i = threadIdx.x; i < 2048; i += 256)
            if (e32[2 * i + 1] != 0) any = 1;
        any = __syncthreads_or(any);
        if (threadIdx.x == 0) g_is64 = any ? 0 : 1;
    }
}

// ---------------- HMMA fp16 QKV projection (single term) ----------------
// Block: 128 rows x 48 cols, K=128. grid=(782,4). 256 threads = 8 warps
// (4M x 2N): warp tile 32x24 = 2x3 m16n8k16 tiles. 47KB smem -> 4 CTAs/SM.
// Epilogue stages results in smem, then writes coalesced streams.
#define PROJ_THREADS 256
#define RPB 128
#define NCB 48
#define KS 136
#define OS 56                          // staging row stride in floats (224B)

#define SM_XH 0
#define SM_WH (SM_XH + RPB * KS)
#define SM_END (SM_WH + NCB * KS)
#define PROJ_SMEM_BYTES (SM_END * 2 + NCB * 4)

#define MMA3(acc, ra0, ra1, ra2, ra3, rb0, rb1)                                  \
    asm volatile("mma.sync.aligned.m16n8k16.row.col.f32.f16.f16.f32 "            \
        "{%0,%1,%2,%3}, {%4,%5,%6,%7}, {%8,%9}, {%0,%1,%2,%3};"                  \
        : "+f"(acc[0]), "+f"(acc[1]), "+f"(acc[2]), "+f"(acc[3])                 \
        : "r"(ra0), "r"(ra1), "r"(ra2), "r"(ra3), "r"(rb0), "r"(rb1))

#define LDSM_X4(r0, r1, r2, r3, addr)                                            \
    asm volatile("ldmatrix.sync.aligned.m8n8.x4.shared.b16 {%0,%1,%2,%3}, [%4];" \
        : "=r"(r0), "=r"(r1), "=r"(r2), "=r"(r3) : "r"(addr))

#define LDSM_X2(r0, r1, addr)                                                    \
    asm volatile("ldmatrix.sync.aligned.m8n8.x2.shared.b16 {%0,%1}, [%2];"       \
        : "=r"(r0), "=r"(r1) : "r"(addr))

__global__ void __launch_bounds__(PROJ_THREADS, 4)
k_proj(const float* __restrict__ bQ, const float* __restrict__ bK,
       const float* __restrict__ bV, float* __restrict__ out_v) {
    extern __shared__ __half sm[];
    float* bsm = (float*)(sm + SM_END);
    float* sout = (float*)sm;          // reused after mainloop: [128][OS] floats

    const int tid = threadIdx.x;
    const int row0 = blockIdx.x * RPB;
    const int by = blockIdx.y;
    const int c0 = by * NCB;

    {
        const uint4* wh_g = (const uint4*)g_wth;
        for (int i = tid; i < NCB * D_IN / 8; i += PROJ_THREADS) {
            int m = i >> 4, c16 = i & 15;
            *(uint4*)(sm + SM_WH + m * KS + c16 * 8) = wh_g[(c0 + m) * 16 + c16];
        }
    }
    {
        const uint4* xh_g = (const uint4*)g_xh;
        const uint4 z = make_uint4(0, 0, 0, 0);
        for (int i = tid; i < RPB * D_IN / 8; i += PROJ_THREADS) {
            int r = i >> 4, c16 = i & 15;
            int row = row0 + r;
            uint4 v = (row < N_NODES) ? xh_g[row * 16 + c16] : z;
            *(uint4*)(sm + SM_XH + r * KS + c16 * 8) = v;
        }
    }
    for (int i = tid; i < NCB; i += PROJ_THREADS) {
        int m = c0 + i;
        bsm[i] = (m < 64) ? bQ[m] : (m < 128 ? bK[m - 64] : bV[m - 128]);
    }
    __syncthreads();

    const int lane = tid & 31;
    const int wid  = tid >> 5;
    const int wm   = wid & 3;
    const int wn   = wid >> 2;
    const int grp  = lane >> 2;
    const int tig  = lane & 3;

    float acc[2][3][4];
#pragma unroll
    for (int mi = 0; mi < 2; mi++)
#pragma unroll
        for (int ni = 0; ni < 3; ni++)
#pragma unroll
            for (int t = 0; t < 4; t++) acc[mi][ni][t] = 0.0f;

    const int a_half = SM_XH + (wm * 32 + (lane & 15)) * KS + ((lane & 16) ? 8 : 0);
    const int b_half = SM_WH + (wn * 24 + (lane & 7)) * KS + ((lane & 8) ? 8 : 0);
    const uint32_t a_base = (uint32_t)__cvta_generic_to_shared(sm + a_half);
    const uint32_t b_base = (uint32_t)__cvta_generic_to_shared(sm + b_half);

#pragma unroll
    for (int k0 = 0; k0 < 8; k0++) {
        const uint32_t kb = k0 * 32;
        uint32_t b[3][2];
#pragma unroll
        for (int ni = 0; ni < 3; ni++)
            LDSM_X2(b[ni][0], b[ni][1], b_base + ni * (8 * KS * 2) + kb);
        uint32_t a[2][4];
#pragma unroll
        for (int mi = 0; mi < 2; mi++)
            LDSM_X4(a[mi][0], a[mi][1], a[mi][2], a[mi][3],
                    a_base + mi * (16 * KS * 2) + kb);
#pragma unroll
        for (int mi = 0; mi < 2; mi++)
#pragma unroll
            for (int ni = 0; ni < 3; ni++)
                MMA3(acc[mi][ni], a[mi][0], a[mi][1], a[mi][2], a[mi][3],
                     b[ni][0], b[ni][1]);
    }

    // ---- stage biased results into smem (mainloop tiles dead now)
    __syncthreads();
#pragma unroll
    for (int mi = 0; mi < 2; mi++) {
#pragma unroll
        for (int ni = 0; ni < 3; ni++) {
            int lc = wn * 24 + ni * 8 + tig * 2;
            float b0 = bsm[lc], b1 = bsm[lc + 1];
#pragma unroll
            for (int half = 0; half < 2; half++) {
                int rl = wm * 32 + mi * 16 + grp + half * 8;
                float2 v;
                v.x = acc[mi][ni][half * 2 + 0] + b0;
                v.y = acc[mi][ni][half * 2 + 1] + b1;
                *(float2*)&sout[rl * OS + lc] = v;
            }
        }
    }
    __syncthreads();

    // ---- coalesced write-out by column slice
    if (by == 0) {
        // q cols 0..47
        for (int i = tid; i < RPB * 24; i += PROJ_THREADS) {
            int r = i / 24, jp = i % 24;
            int row = row0 + r;
            if (row < N_NODES) {
                float2 v = *(float2*)&sout[r * OS + jp * 2];
                *(__half2*)(g_qh + row * 64 + jp * 2) = __floats2half2_rn(v.x, v.y);
            }
        }
    } else if (by == 1) {
        // q cols 48..63 (jp 0..7), k cols 0..31 (jp 8..23)
        for (int i = tid; i < RPB * 24; i += PROJ_THREADS) {
            int r = i / 24, jp = i % 24;
            int row = row0 + r;
            if (row < N_NODES) {
                float2 v = *(float2*)&sout[r * OS + jp * 2];
                __half2 hv = __floats2half2_rn(v.x, v.y);
                if (jp < 8) *(__half2*)(g_qh + row * 64 + 48 + jp * 2) = hv;
                else        *(__half2*)(g_kh + row * 64 + (jp - 8) * 2) = hv;
            }
        }
    } else if (by == 2) {
        // k cols 32..63 (lc 0..31), v head-0 cc 0..15 (lc 32..47)
        for (int i = tid; i < RPB * 16; i += PROJ_THREADS) {
            int r = i / 16, jp = i % 16;
            int row = row0 + r;
            if (row < N_NODES) {
                float2 v = *(float2*)&sout[r * OS + jp * 2];
                *(__half2*)(g_kh + row * 64 + 32 + jp * 2) = __floats2half2_rn(v.x, v.y);
            }
        }
        for (int i = tid; i < RPB * 16; i += PROJ_THREADS) {
            int r = i / 16, dd = i % 16;
            int row = row0 + r;
            if (row < N_NODES)
                out_v[(size_t)row * 64 + dd * 4] = sout[r * OS + 32 + dd];
        }
    } else {
        // v cc 16..63 in output-offset order: j -> o=4g+m+1, lc=m*16+g
        for (int i = tid; i < RPB * 48; i += PROJ_THREADS) {
            int r = i / 48, j = i % 48;
            int row = row0 + r;
            if (row < N_NODES) {
                int g = j / 3, m = j - g * 3;
                out_v[(size_t)row * 64 + g * 4 + m + 1] = sout[r * OS + m * 16 + g];
            }
        }
    }
}

// ---------------- edge pass 1: prods + segment exp-sums (8 edges/thread) ----
__global__ void k_edge1(const void* __restrict__ edge_raw,
                        float* __restrict__ out_prods) {
    int t = blockIdx.x * blockDim.x + threadIdx.x;
    int p = t >> 3;
    if (p >= EO) return;
    int sub = t & 7;

    int src[8], dst[8];
    if (g_is64) {
        const long long* ed = (const long long*)edge_raw;
#pragma unroll
        for (int i = 0; i < 8; i++) {
            src[i] = (int)ed[p + i * EO];
            dst[i] = (int)ed[N_EDGES + p + i * EO];
        }
    } else {
        const int* ed = (const int*)edge_raw;
#pragma unroll
        for (int i = 0; i < 8; i++) {
            src[i] = ed[p + i * EO];
            dst[i] = ed[N_EDGES + p + i * EO];
        }
    }

    uint4 qv[8], kv[8];
#pragma unroll
    for (int i = 0; i < 8; i++) {
        qv[i] = *(const uint4*)(g_qh + src[i] * 64 + sub * 8);
        kv[i] = *(const uint4*)(g_kh + dst[i] * 64 + sub * 8);
    }

    float dot[8];
#pragma unroll
    for (int i = 0; i < 8; i++) {
        const __half2* q = reinterpret_cast<const __half2*>(&qv[i]);
        const __half2* k = reinterpret_cast<const __half2*>(&kv[i]);
        __half2 a = __hmul2(q[0], k[0]);
        a = __hfma2(q[1], k[1], a);
        a = __hfma2(q[2], k[2], a);
        a = __hfma2(q[3], k[3], a);
        float d = __low2float(a) + __high2float(a);
        dot[i] = d + __shfl_xor_sync(0xffffffffu, d, 1);
    }

    if ((sub & 1) == 0) {
        int h = sub >> 1;
#pragma unroll
        for (int i = 0; i < 8; i++) {
            float pr = dot[i] * 0.25f;         // 1/sqrt(16)
            out_prods[(p + i * EO) * 4 + h] = pr;
            atomicAdd(&g_sum[src[i] * 4 + h], __expf(pr));
        }
    }
}

// ---------------- reciprocal pass: g_sum -> 1/(g_sum + eps) (float4) -------
#define RCP_BLOCKS ((NH / 4 + 255) / 256)               // 391
__global__ void k_rcp() {
    int i = blockIdx.x * blockDim.x + threadIdx.x;
    if (i >= NH / 4) return;
    float4 s = reinterpret_cast<const float4*>(g_sum)[i];
    float4 r;
    r.x = __frcp_rn(s.x + 1e-16f);
    r.y = __frcp_rn(s.y + 1e-16f);
    r.z = __frcp_rn(s.z + 1e-16f);
    r.w = __frcp_rn(s.w + 1e-16f);
    reinterpret_cast<float4*>(g_sum)[i] = r;
}

// ---------------- edge pass 2: att = exp(prods) * rsum[src] (4 edges/thr) --
__global__ void k_edge2(const void* __restrict__ edge_raw,
                        const float* __restrict__ out_prods,
                        float* __restrict__ out_att) {
    int p = blockIdx.x * blockDim.x + threadIdx.x;
    if (p >= EQ) return;

    int src[4];
    if (g_is64) {
        const long long* ed = (const long long*)edge_raw;
#pragma unroll
        for (int i = 0; i < 4; i++) src[i] = (int)ed[p + i * EQ];
    } else {
        const int* ed = (const int*)edge_raw;
#pragma unroll
        for (int i = 0; i < 4; i++) src[i] = ed[p + i * EQ];
    }

    float4 pr[4], s[4];
#pragma unroll
    for (int i = 0; i < 4; i++) {
        pr[i] = reinterpret_cast<const float4*>(out_prods)[p + i * EQ];
        s[i]  = reinterpret_cast<const float4*>(g_sum)[src[i]];
    }
#pragma unroll
    for (int i = 0; i < 4; i++) {
        float4 r;
        r.x = __expf(pr[i].x) * s[i].x;
        r.y = __expf(pr[i].y) * s[i].y;
        r.z = __expf(pr[i].z) * s[i].z;
        r.w = __expf(pr[i].w) * s[i].w;
        reinterpret_cast<float4*>(out_att)[p + i * EQ] = r;
    }
}

// ---------------- launch ----------------
extern "C" void kernel_launch(void* const* d_in, const int* in_sizes, int n_in,
                              void* d_out, int out_size) {
    const float* x  = (const float*)d_in[0];
    const void*  edge = d_in[1];
    const float* WQ = (const float*)d_in[2];
    const float* bQ = (const float*)d_in[3];
    const float* WK = (const float*)d_in[4];
    const float* bK = (const float*)d_in[5];
    const float* WV = (const float*)d_in[6];
    const float* bV = (const float*)d_in[7];

    float* out       = (float*)d_out;
    float* out_att   = out;                                   // [E, 4]
    float* out_v     = out + (size_t)EH;                      // [N, 16, 4]
    float* out_prods = out_v + (size_t)N_NODES * ATT;         // [E, 4]

    cudaFuncSetAttribute(k_proj, cudaFuncAttributeMaxDynamicSharedMemorySize,
                         PROJ_SMEM_BYTES);

    k_prep<<<PREP_BLOCKS, 256>>>(x, WQ, WK, WV, (const int*)edge);

    dim3 pg((N_NODES + RPB - 1) / RPB, 4);                    // (782, 4)
    k_proj<<<pg, PROJ_THREADS, PROJ_SMEM_BYTES>>>(bQ, bK, bV, out_v);

    int nt1 = EO * 8;
    k_edge1<<<(nt1 + 255) / 256, 256>>>(edge, out_prods);
    k_rcp<<<RCP_BLOCKS, 256>>>();
    k_edge2<<<(EQ + 255) / 256, 256>>>(edge, out_prods, out_att);
}

// round 17
// speedup vs baseline: 1.0872x; 1.0872x over previous
#include <cuda_runtime.h>
#include <cuda_fp16.h>
#include <cstdint>

#define N_NODES 100000
#define N_EDGES 3200000
#define D_IN 128
#define ATT 64
#define HEADS 4
#define NH (N_NODES * HEADS)
#define EH (N_EDGES * HEADS)
#define COLS 192
#define EQ (N_EDGES / 4)
#define EO (N_EDGES / 8)

// ---------------- scratch (device globals; no allocation) ----------------
__device__ __align__(128) __half g_qh[(size_t)N_NODES * ATT];   // fp16 q rows (128B/row)
__device__ __align__(128) __half g_kh[(size_t)N_NODES * ATT];   // fp16 k rows
__device__ __align__(128) __half g_xh[(size_t)N_NODES * D_IN];  // fp16 x (precomputed)
__device__ __align__(16)  float  g_sum[NH];
__device__ int g_is64;
// fused transposed weights fp16: Wt[m][d]
__device__ __align__(16) __half g_wth[COLS * D_IN];

// ---------------- fused prep: xh | zero | wconv | detect (one launch) ------
#define XH_CHUNKS   (N_NODES * D_IN / 8)                // 1.6M
#define XH_QUARTER  (XH_CHUNKS / 4)
#define XH_BLOCKS   ((XH_QUARTER + 255) / 256)          // 1563
#define ZERO_BLOCKS ((NH + 255) / 256)                  // 1563
#define WC_BLOCKS   ((COLS * D_IN + 255) / 256)         // 96
#define PREP_BLOCKS (XH_BLOCKS + ZERO_BLOCKS + WC_BLOCKS + 1)

__global__ void k_prep(const float* __restrict__ x,
                       const float* __restrict__ WQ, const float* __restrict__ WK,
                       const float* __restrict__ WV, const int* __restrict__ e32) {
    int b = blockIdx.x;
    if (b < XH_BLOCKS) {
        int i0 = b * 256 + threadIdx.x;
        if (i0 < XH_QUARTER) {
#pragma unroll
            for (int c = 0; c < 4; c++) {
                int i = i0 + c * XH_QUARTER;
                const float4* xp = (const float4*)(x + (size_t)i * 8);
                float4 v0 = xp[0], v1 = xp[1];
                __half hi[8];
                hi[0] = __float2half_rn(v0.x); hi[1] = __float2half_rn(v0.y);
                hi[2] = __float2half_rn(v0.z); hi[3] = __float2half_rn(v0.w);
                hi[4] = __float2half_rn(v1.x); hi[5] = __float2half_rn(v1.y);
                hi[6] = __float2half_rn(v1.z); hi[7] = __float2half_rn(v1.w);
                ((uint4*)g_xh)[i] = *(const uint4*)hi;
            }
        }
    } else if (b < XH_BLOCKS + ZERO_BLOCKS) {
        int j = (b - XH_BLOCKS) * 256 + threadIdx.x;
        if (j < NH) g_sum[j] = 0.0f;
    } else if (b < XH_BLOCKS + ZERO_BLOCKS + WC_BLOCKS) {
        int i = (b - XH_BLOCKS - ZERO_BLOCKS) * 256 + threadIdx.x;
        if (i < COLS * D_IN) {
            int m = i >> 7, d = i & 127;
            float w;
            if (m < 64)       w = WQ[d * 64 + m];
            else if (m < 128) w = WK[d * 64 + (m - 64)];
            else              w = WV[d * 64 + (m - 128)];
            g_wth[i] = __float2half_rn(w);
        }
    } else {
        // edge dtype detect: int64 edges (<1e5) have zero high words
        int any = 0;
        for (int i = threadIdx.x; i < 2048; i += 256)
            if (e32[2 * i + 1] != 0) any = 1;
        any = __syncthreads_or(any);
        if (threadIdx.x == 0) g_is64 = any ? 0 : 1;
    }
}

// ---------------- HMMA fp16 QKV projection (single term) ----------------
// Block: 128 rows x 64 cols, K=128. grid=(782,3): slice 0=Q, 1=K, 2=V.
// 256 threads = 8 warps (4M x 2N): warp tile 32x32 = 2x4 m16n8k16 tiles.
// 51.3KB smem -> 4 CTAs/SM. Epilogue stages in smem, writes coalesced.
#define PROJ_THREADS 256
#define RPB 128
#define NCB 64
#define KS 136
#define OS 66                          // staging row stride in floats

#define SM_XH 0
#define SM_WH (SM_XH + RPB * KS)                  // 17408
#define SM_END (SM_WH + NCB * KS)                 // 26112 halfs
#define PROJ_SMEM_BYTES (SM_END * 2 + NCB * 4)

#define MMA3(acc, ra0, ra1, ra2, ra3, rb0, rb1)                                  \
    asm volatile("mma.sync.aligned.m16n8k16.row.col.f32.f16.f16.f32 "            \
        "{%0,%1,%2,%3}, {%4,%5,%6,%7}, {%8,%9}, {%0,%1,%2,%3};"                  \
        : "+f"(acc[0]), "+f"(acc[1]), "+f"(acc[2]), "+f"(acc[3])                 \
        : "r"(ra0), "r"(ra1), "r"(ra2), "r"(ra3), "r"(rb0), "r"(rb1))

#define LDSM_X4(r0, r1, r2, r3, addr)                                            \
    asm volatile("ldmatrix.sync.aligned.m8n8.x4.shared.b16 {%0,%1,%2,%3}, [%4];" \
        : "=r"(r0), "=r"(r1), "=r"(r2), "=r"(r3) : "r"(addr))

#define LDSM_X2(r0, r1, addr)                                                    \
    asm volatile("ldmatrix.sync.aligned.m8n8.x2.shared.b16 {%0,%1}, [%2];"       \
        : "=r"(r0), "=r"(r1) : "r"(addr))

__global__ void __launch_bounds__(PROJ_THREADS, 4)
k_proj(const float* __restrict__ bQ, const float* __restrict__ bK,
       const float* __restrict__ bV, float* __restrict__ out_v) {
    extern __shared__ __half sm[];
    float* bsm = (float*)(sm + SM_END);
    float* sout = (float*)sm;          // reused after mainloop: [128][OS] floats

    const int tid = threadIdx.x;
    const int row0 = blockIdx.x * RPB;
    const int by = blockIdx.y;         // 0=Q, 1=K, 2=V
    const int c0 = by * NCB;

    // ---- stage W slice (fp16 global -> padded smem)
    {
        const uint4* wh_g = (const uint4*)g_wth;
        for (int i = tid; i < NCB * D_IN / 8; i += PROJ_THREADS) {
            int m = i >> 4, c16 = i & 15;
            *(uint4*)(sm + SM_WH + m * KS + c16 * 8) = wh_g[(c0 + m) * 16 + c16];
        }
    }
    // ---- stage x tile (fp16)
    {
        const uint4* xh_g = (const uint4*)g_xh;
        const uint4 z = make_uint4(0, 0, 0, 0);
        for (int i = tid; i < RPB * D_IN / 8; i += PROJ_THREADS) {
            int r = i >> 4, c16 = i & 15;
            int row = row0 + r;
            uint4 v = (row < N_NODES) ? xh_g[row * 16 + c16] : z;
            *(uint4*)(sm + SM_XH + r * KS + c16 * 8) = v;
        }
    }
    {
        const float* bsrc = (by == 0) ? bQ : (by == 1 ? bK : bV);
        for (int i = tid; i < NCB; i += PROJ_THREADS) bsm[i] = bsrc[i];
    }
    __syncthreads();

    const int lane = tid & 31;
    const int wid  = tid >> 5;
    const int wm   = wid & 3;          // 32-row strip
    const int wn   = wid >> 2;         // 32-col strip
    const int grp  = lane >> 2;
    const int tig  = lane & 3;

    float acc[2][4][4];
#pragma unroll
    for (int mi = 0; mi < 2; mi++)
#pragma unroll
        for (int ni = 0; ni < 4; ni++)
#pragma unroll
            for (int t = 0; t < 4; t++) acc[mi][ni][t] = 0.0f;

    const int a_half = SM_XH + (wm * 32 + (lane & 15)) * KS + ((lane & 16) ? 8 : 0);
    const int b_half = SM_WH + (wn * 32 + (lane & 7)) * KS + ((lane & 8) ? 8 : 0);
    const uint32_t a_base = (uint32_t)__cvta_generic_to_shared(sm + a_half);
    const uint32_t b_base = (uint32_t)__cvta_generic_to_shared(sm + b_half);

#pragma unroll
    for (int k0 = 0; k0 < 8; k0++) {
        const uint32_t kb = k0 * 32;
        uint32_t b[4][2];
#pragma unroll
        for (int ni = 0; ni < 4; ni++)
            LDSM_X2(b[ni][0], b[ni][1], b_base + ni * (8 * KS * 2) + kb);
        uint32_t a[2][4];
#pragma unroll
        for (int mi = 0; mi < 2; mi++)
            LDSM_X4(a[mi][0], a[mi][1], a[mi][2], a[mi][3],
                    a_base + mi * (16 * KS * 2) + kb);
#pragma unroll
        for (int mi = 0; mi < 2; mi++)
#pragma unroll
            for (int ni = 0; ni < 4; ni++)
                MMA3(acc[mi][ni], a[mi][0], a[mi][1], a[mi][2], a[mi][3],
                     b[ni][0], b[ni][1]);
    }

    // ---- stage biased results into smem (mainloop tiles dead now)
    __syncthreads();
#pragma unroll
    for (int mi = 0; mi < 2; mi++) {
#pragma unroll
        for (int ni = 0; ni < 4; ni++) {
            int lc = wn * 32 + ni * 8 + tig * 2;
            float b0 = bsm[lc], b1 = bsm[lc + 1];
#pragma unroll
            for (int half = 0; half < 2; half++) {
                int rl = wm * 32 + mi * 16 + grp + half * 8;
                float2 v;
                v.x = acc[mi][ni][half * 2 + 0] + b0;
                v.y = acc[mi][ni][half * 2 + 1] + b1;
                *(float2*)&sout[rl * OS + lc] = v;
            }
        }
    }
    __syncthreads();

    // ---- coalesced write-out per slice
    if (by == 0) {
        // Q: half2 stream
        for (int i = tid; i < RPB * 32; i += PROJ_THREADS) {
            int r = i >> 5, jp = i & 31;
            int row = row0 + r;
            if (row < N_NODES) {
                float2 v = *(float2*)&sout[r * OS + jp * 2];
                *(__half2*)(g_qh + row * 64 + jp * 2) = __floats2half2_rn(v.x, v.y);
            }
        }
    } else if (by == 1) {
        // K: half2 stream
        for (int i = tid; i < RPB * 32; i += PROJ_THREADS) {
            int r = i >> 5, jp = i & 31;
            int row = row0 + r;
            if (row < N_NODES) {
                float2 v = *(float2*)&sout[r * OS + jp * 2];
                *(__half2*)(g_kh + row * 64 + jp * 2) = __floats2half2_rn(v.x, v.y);
            }
        }
    } else {
        // V: out_v[row*64 + o], o = dd*4 + h, lc = h*16 + dd -> coalesced fp32
        for (int i = tid; i < RPB * 64; i += PROJ_THREADS) {
            int r = i >> 6, o = i & 63;
            int row = row0 + r;
            if (row < N_NODES) {
                int dd = o >> 2, h = o & 3;
                out_v[(size_t)row * 64 + o] = sout[r * OS + h * 16 + dd];
            }
        }
    }
}

// ---------------- edge pass 1: prods + segment exp-sums (8 edges/thread) ----
__global__ void k_edge1(const void* __restrict__ edge_raw,
                        float* __restrict__ out_prods) {
    int t = blockIdx.x * blockDim.x + threadIdx.x;
    int p = t >> 3;
    if (p >= EO) return;
    int sub = t & 7;

    int src[8], dst[8];
    if (g_is64) {
        const long long* ed = (const long long*)edge_raw;
#pragma unroll
        for (int i = 0; i < 8; i++) {
            src[i] = (int)ed[p + i * EO];
            dst[i] = (int)ed[N_EDGES + p + i * EO];
        }
    } else {
        const int* ed = (const int*)edge_raw;
#pragma unroll
        for (int i = 0; i < 8; i++) {
            src[i] = ed[p + i * EO];
            dst[i] = ed[N_EDGES + p + i * EO];
        }
    }

    uint4 qv[8], kv[8];
#pragma unroll
    for (int i = 0; i < 8; i++) {
        qv[i] = *(const uint4*)(g_qh + src[i] * 64 + sub * 8);
        kv[i] = *(const uint4*)(g_kh + dst[i] * 64 + sub * 8);
    }

    float dot[8];
#pragma unroll
    for (int i = 0; i < 8; i++) {
        const __half2* q = reinterpret_cast<const __half2*>(&qv[i]);
        const __half2* k = reinterpret_cast<const __half2*>(&kv[i]);
        __half2 a = __hmul2(q[0], k[0]);
        a = __hfma2(q[1], k[1], a);
        a = __hfma2(q[2], k[2], a);
        a = __hfma2(q[3], k[3], a);
        float d = __low2float(a) + __high2float(a);
        dot[i] = d + __shfl_xor_sync(0xffffffffu, d, 1);
    }

    if ((sub & 1) == 0) {
        int h = sub >> 1;
#pragma unroll
        for (int i = 0; i < 8; i++) {
            float pr = dot[i] * 0.25f;         // 1/sqrt(16)
            out_prods[(p + i * EO) * 4 + h] = pr;
            atomicAdd(&g_sum[src[i] * 4 + h], __expf(pr));
        }
    }
}

// ---------------- edge pass 2: att = exp(prods)/sum[src] (4 edges/thread) ---
__global__ void k_edge2(const void* __restrict__ edge_raw,
                        const float* __restrict__ out_prods,
                        float* __restrict__ out_att) {
    int p = blockIdx.x * blockDim.x + threadIdx.x;
    if (p >= EQ) return;

    int src[4];
    if (g_is64) {
        const long long* ed = (const long long*)edge_raw;
#pragma unroll
        for (int i = 0; i < 4; i++) src[i] = (int)ed[p + i * EQ];
    } else {
        const int* ed = (const int*)edge_raw;
#pragma unroll
        for (int i = 0; i < 4; i++) src[i] = ed[p + i * EQ];
    }

    float4 pr[4], s[4];
#pragma unroll
    for (int i = 0; i < 4; i++) {
        pr[i] = reinterpret_cast<const float4*>(out_prods)[p + i * EQ];
        s[i]  = reinterpret_cast<const float4*>(g_sum)[src[i]];
    }
#pragma unroll
    for (int i = 0; i < 4; i++) {
        float4 r;
        r.x = __fdividef(__expf(pr[i].x), s[i].x + 1e-16f);
        r.y = __fdividef(__expf(pr[i].y), s[i].y + 1e-16f);
        r.z = __fdividef(__expf(pr[i].z), s[i].z + 1e-16f);
        r.w = __fdividef(__expf(pr[i].w), s[i].w + 1e-16f);
        reinterpret_cast<float4*>(out_att)[p + i * EQ] = r;
    }
}

// ---------------- launch ----------------
extern "C" void kernel_launch(void* const* d_in, const int* in_sizes, int n_in,
                              void* d_out, int out_size) {
    const float* x  = (const float*)d_in[0];
    const void*  edge = d_in[1];
    const float* WQ = (const float*)d_in[2];
    const float* bQ = (const float*)d_in[3];
    const float* WK = (const float*)d_in[4];
    const float* bK = (const float*)d_in[5];
    const float* WV = (const float*)d_in[6];
    const float* bV = (const float*)d_in[7];

    float* out       = (float*)d_out;
    float* out_att   = out;                                   // [E, 4]
    float* out_v     = out + (size_t)EH;                      // [N, 16, 4]
    float* out_prods = out_v + (size_t)N_NODES * ATT;         // [E, 4]

    cudaFuncSetAttribute(k_proj, cudaFuncAttributeMaxDynamicSharedMemorySize,
                         PROJ_SMEM_BYTES);

    k_prep<<<PREP_BLOCKS, 256>>>(x, WQ, WK, WV, (const int*)edge);

    dim3 pg((N_NODES + RPB - 1) / RPB, 3);                    // (782, 3)
    k_proj<<<pg, PROJ_THREADS, PROJ_SMEM_BYTES>>>(bQ, bK, bV, out_v);

    int nt1 = EO * 8;
    k_edge1<<<(nt1 + 255) / 256, 256>>>(edge, out_prods);
    k_edge2<<<(EQ + 255) / 256, 256>>>(edge, out_prods, out_att);
}